// round 3
// baseline (speedup 1.0000x reference)
#include <cuda_runtime.h>
#include <cuda_bf16.h>

#define LOG2E 1.4426950408889634f

typedef unsigned long long u64;

__device__ __forceinline__ u64 pk2(float lo, float hi) {
    u64 r; asm("mov.b64 %0, {%1, %2};" : "=l"(r) : "f"(lo), "f"(hi)); return r;
}
__device__ __forceinline__ void upk2(float& lo, float& hi, u64 v) {
    asm("mov.b64 {%0, %1}, %2;" : "=f"(lo), "=f"(hi) : "l"(v));
}
__device__ __forceinline__ u64 ffma2(u64 a, u64 b, u64 c) {
    u64 d; asm("fma.rn.f32x2 %0, %1, %2, %3;" : "=l"(d) : "l"(a), "l"(b), "l"(c)); return d;
}
__device__ __forceinline__ u64 fadd2(u64 a, u64 b) {
    u64 d; asm("add.rn.f32x2 %0, %1, %2;" : "=l"(d) : "l"(a), "l"(b)); return d;
}
__device__ __forceinline__ u64 fmul2(u64 a, u64 b) {
    u64 d; asm("mul.rn.f32x2 %0, %1, %2;" : "=l"(d) : "l"(a), "l"(b)); return d;
}
__device__ __forceinline__ float sqrt_ap(float x) {
    float d; asm("sqrt.approx.f32 %0, %1;" : "=f"(d) : "f"(x)); return d;
}
__device__ __forceinline__ float ex2_ap(float x) {
    float e; asm("ex2.approx.f32 %0, %1;" : "=f"(e) : "f"(x)); return e;
}

__global__ __launch_bounds__(128)
void initlayer_kernel(const float* __restrict__ R,
                      const float* __restrict__ coords,
                      const float* __restrict__ W,
                      float* __restrict__ out,
                      int A, int G) {
    // Pair-packed atom data: smem[2p]   = (px0,px1,py0,py1)
    //                        smem[2p+1] = (pz0,pz1,pw0,pw1), pw = |p'|^2
    extern __shared__ float4 sm4[];
    float* smf = (float*)sm4;

    const int b = blockIdx.y;
    const int g = blockIdx.x * blockDim.x + threadIdx.x;

    // Weight pre-scaled by log2(e): exp(||W(c-r)||) = ex2(||W'(c-r)||).
    const float w00 = W[0] * LOG2E, w01 = W[1] * LOG2E, w02 = W[2] * LOG2E;
    const float w10 = W[3] * LOG2E, w11 = W[4] * LOG2E, w12 = W[5] * LOG2E;
    const float w20 = W[6] * LOG2E, w21 = W[7] * LOG2E, w22 = W[8] * LOG2E;

    // Prologue: transform atoms, store pair-packed (p', |p'|^2).
    for (int a = threadIdx.x; a < A; a += blockDim.x) {
        const float* r = R + ((long)b * A + a) * 3;
        float rx = r[0], ry = r[1], rz = r[2];
        float px = fmaf(w00, rx, fmaf(w01, ry, w02 * rz));
        float py = fmaf(w10, rx, fmaf(w11, ry, w12 * rz));
        float pz = fmaf(w20, rx, fmaf(w21, ry, w22 * rz));
        float pw = fmaf(px, px, fmaf(py, py, pz * pz));
        int p = a >> 1, h = a & 1;
        float* base = smf + p * 8;
        base[0 + h] = px;
        base[2 + h] = py;
        base[4 + h] = pz;
        base[6 + h] = pw;
    }
    __syncthreads();

    if (g >= G) return;

    // q' = log2e * W @ coords[g]
    const float cx = coords[g * 3 + 0];
    const float cy = coords[g * 3 + 1];
    const float cz = coords[g * 3 + 2];
    const float qx = fmaf(w00, cx, fmaf(w01, cy, w02 * cz));
    const float qy = fmaf(w10, cx, fmaf(w11, cy, w12 * cz));
    const float qz = fmaf(w20, cx, fmaf(w21, cy, w22 * cz));
    const float qn = fmaf(qx, qx, fmaf(qy, qy, qz * qz));

    const u64 m2x2 = pk2(-2.0f * qx, -2.0f * qx);
    const u64 m2y2 = pk2(-2.0f * qy, -2.0f * qy);
    const u64 m2z2 = pk2(-2.0f * qz, -2.0f * qz);
    const u64 qn2  = pk2(qn, qn);
    const u64 cMH2 = pk2(-0.5f, -0.5f);
    const u64 c152 = pk2(1.5f, 1.5f);

    float acc0 = 0.0f, acc1 = 0.0f, acc2 = 0.0f, acc3 = 0.0f;

    const int npairs = A >> 1;
    int p = 0;
    #pragma unroll 2
    for (; p + 2 <= npairs; p += 2) {
        // ---- pair p: MUFU sqrt path ----
        {
            float4 PA = sm4[2 * p + 0];
            float4 PB = sm4[2 * p + 1];
            u64 px2 = pk2(PA.x, PA.y), py2 = pk2(PA.z, PA.w);
            u64 pz2 = pk2(PB.x, PB.y), pw2 = pk2(PB.z, PB.w);
            u64 u = ffma2(m2z2, pz2, pw2);
            u = ffma2(m2y2, py2, u);
            u = ffma2(m2x2, px2, u);
            u = fadd2(u, qn2);
            float s0, s1; upk2(s0, s1, u);
            s0 = fmaxf(s0, 1e-12f);
            s1 = fmaxf(s1, 1e-12f);
            acc0 += ex2_ap(sqrt_ap(s0));
            acc1 += ex2_ap(sqrt_ap(s1));
        }
        // ---- pair p+1: fma-pipe Newton sqrt path ----
        {
            float4 PA = sm4[2 * p + 2];
            float4 PB = sm4[2 * p + 3];
            u64 px2 = pk2(PA.x, PA.y), py2 = pk2(PA.z, PA.w);
            u64 pz2 = pk2(PB.x, PB.y), pw2 = pk2(PB.z, PB.w);
            u64 u = ffma2(m2z2, pz2, pw2);
            u = ffma2(m2y2, py2, u);
            u = ffma2(m2x2, px2, u);
            u = fadd2(u, qn2);
            float s0, s1; upk2(s0, s1, u);
            s0 = fmaxf(s0, 1e-12f);
            s1 = fmaxf(s1, 1e-12f);
            // rsqrt bithack seeds (alu pipe)
            float y0 = __int_as_float(0x5f3759df - (__float_as_int(s0) >> 1));
            float y1 = __int_as_float(0x5f3759df - (__float_as_int(s1) >> 1));
            u64 s2 = pk2(s0, s1);
            u64 y2 = pk2(y0, y1);
            u64 h2 = fmul2(s2, cMH2);          // -0.5*s
            // Newton iter 1: y *= 1.5 + h*y*y
            u64 t2 = fmul2(y2, y2);
            u64 w2 = ffma2(h2, t2, c152);
            y2 = fmul2(y2, w2);
            // Newton iter 2
            t2 = fmul2(y2, y2);
            w2 = ffma2(h2, t2, c152);
            y2 = fmul2(y2, w2);
            u64 d2 = fmul2(s2, y2);            // d = s * rsqrt(s) = sqrt(s)
            float d0, d1; upk2(d0, d1, d2);
            acc2 += ex2_ap(d0);
            acc3 += ex2_ap(d1);
        }
    }
    // Leftover pair (MUFU path)
    for (; p < npairs; ++p) {
        float4 PA = sm4[2 * p + 0];
        float4 PB = sm4[2 * p + 1];
        u64 px2 = pk2(PA.x, PA.y), py2 = pk2(PA.z, PA.w);
        u64 pz2 = pk2(PB.x, PB.y), pw2 = pk2(PB.z, PB.w);
        u64 u = ffma2(m2z2, pz2, pw2);
        u = ffma2(m2y2, py2, u);
        u = ffma2(m2x2, px2, u);
        u = fadd2(u, qn2);
        float s0, s1; upk2(s0, s1, u);
        acc0 += ex2_ap(sqrt_ap(fmaxf(s0, 1e-12f)));
        acc1 += ex2_ap(sqrt_ap(fmaxf(s1, 1e-12f)));
    }
    // Leftover odd atom
    if (A & 1) {
        int a = A - 1;
        float px = smf[(a >> 1) * 8 + 0], py = smf[(a >> 1) * 8 + 2];
        float pz = smf[(a >> 1) * 8 + 4], pw = smf[(a >> 1) * 8 + 6];
        float s = fmaf(-2.0f * qx, px, fmaf(-2.0f * qy, py, fmaf(-2.0f * qz, pz, qn + pw)));
        acc0 += ex2_ap(sqrt_ap(fmaxf(s, 1e-12f)));
    }

    out[(long)b * G + g] = (acc0 + acc1) + (acc2 + acc3);
}

extern "C" void kernel_launch(void* const* d_in, const int* in_sizes, int n_in,
                              void* d_out, int out_size) {
    const float* R      = (const float*)d_in[0];  // (B, A, 3) f32
    const float* coords = (const float*)d_in[1];  // (G, 3)    f32
    const float* W      = (const float*)d_in[2];  // (3, 3)    f32

    const int A = in_sizes[3];
    const int B = in_sizes[0] / (3 * A);
    const int G = in_sizes[1] / 3;

    float* out = (float*)d_out;  // (B, G) f32

    const int threads = 128;
    dim3 grid((G + threads - 1) / threads, B);
    size_t smem = (size_t)((A + 1) / 2) * 2 * sizeof(float4);

    initlayer_kernel<<<grid, threads, smem>>>(R, coords, W, out, A, G);
}

// round 4
// speedup vs baseline: 1.0755x; 1.0755x over previous
#include <cuda_runtime.h>
#include <cuda_bf16.h>

#define LOG2E 1.4426950408889634f

__device__ __forceinline__ float sqrt_ap(float x) {
    float d; asm("sqrt.approx.f32 %0, %1;" : "=f"(d) : "f"(x)); return d;
}
__device__ __forceinline__ float ex2_ap(float x) {
    float e; asm("ex2.approx.f32 %0, %1;" : "=f"(e) : "f"(x)); return e;
}

// 256 threads per CTA, 128 grid points per CTA, 2 threads per grid point
// (each covers half the atoms). Doubles resident warps vs 1-thread-per-g:
// ~55 warps/SM, enough to saturate the MUFU (SQRT+EX2) pipe.
#define GPB 128  // grid points per block

__global__ __launch_bounds__(256)
void initlayer_kernel(const float* __restrict__ R,
                      const float* __restrict__ coords,
                      const float* __restrict__ W,
                      float* __restrict__ out,
                      int A, int G) {
    extern __shared__ float smem[];
    float4* sp = (float4*)smem;            // A entries: (p'x,p'y,p'z,|p'|^2)
    float*  red = smem + 4 * A;            // GPB floats: partial-sum exchange

    const int tid  = threadIdx.x;
    const int b    = blockIdx.y;
    const int gl   = tid & (GPB - 1);      // grid point within block
    const int half = tid >> 7;             // which atom half this thread owns
    const int g    = blockIdx.x * GPB + gl;

    // Weight pre-scaled by log2(e): exp(||W(c-r)||) == ex2(||W'(c-r)||).
    const float w00 = W[0] * LOG2E, w01 = W[1] * LOG2E, w02 = W[2] * LOG2E;
    const float w10 = W[3] * LOG2E, w11 = W[4] * LOG2E, w12 = W[5] * LOG2E;
    const float w20 = W[6] * LOG2E, w21 = W[7] * LOG2E, w22 = W[8] * LOG2E;

    // Prologue: transform this batch's atoms into smem (1 atom/thread here).
    for (int a = tid; a < A; a += blockDim.x) {
        const float* r = R + ((long)b * A + a) * 3;
        float rx = r[0], ry = r[1], rz = r[2];
        float px = fmaf(w00, rx, fmaf(w01, ry, w02 * rz));
        float py = fmaf(w10, rx, fmaf(w11, ry, w12 * rz));
        float pz = fmaf(w20, rx, fmaf(w21, ry, w22 * rz));
        float pw = fmaf(px, px, fmaf(py, py, pz * pz));
        sp[a] = make_float4(px, py, pz, pw);
    }
    __syncthreads();

    float result = 0.0f;
    if (g < G) {
        // q' = log2e * W @ coords[g]  (both half-threads recompute; cheap)
        const float cx = coords[g * 3 + 0];
        const float cy = coords[g * 3 + 1];
        const float cz = coords[g * 3 + 2];
        const float qx = fmaf(w00, cx, fmaf(w01, cy, w02 * cz));
        const float qy = fmaf(w10, cx, fmaf(w11, cy, w12 * cz));
        const float qz = fmaf(w20, cx, fmaf(w21, cy, w22 * cz));
        const float qn = fmaf(qx, qx, fmaf(qy, qy, qz * qz));
        const float m2x = -2.0f * qx;
        const float m2y = -2.0f * qy;
        const float m2z = -2.0f * qz;

        // This thread's atom range: [a0, a1)
        const int ahalf = A >> 1;
        const int a0 = half ? ahalf : 0;
        const int a1 = half ? A : ahalf;

        float acc0 = 0.0f, acc1 = 0.0f, acc2 = 0.0f, acc3 = 0.0f;

        int a = a0;
        for (; a + 4 <= a1; a += 4) {
            float accs[4];
            #pragma unroll
            for (int j = 0; j < 4; ++j) {
                float4 p = sp[a + j];
                // s = |q'|^2 + |p'|^2 - 2 q'.p'
                float s = fmaf(m2x, p.x, fmaf(m2y, p.y, fmaf(m2z, p.z, qn + p.w)));
                s = fmaxf(s, 0.0f);
                accs[j] = ex2_ap(sqrt_ap(s));
            }
            acc0 += accs[0];
            acc1 += accs[1];
            acc2 += accs[2];
            acc3 += accs[3];
        }
        for (; a < a1; ++a) {
            float4 p = sp[a];
            float s = fmaf(m2x, p.x, fmaf(m2y, p.y, fmaf(m2z, p.z, qn + p.w)));
            s = fmaxf(s, 0.0f);
            acc0 += ex2_ap(sqrt_ap(s));
        }
        result = (acc0 + acc1) + (acc2 + acc3);
    }

    // Combine the two atom-half partials and write once.
    if (half == 1) red[gl] = result;
    __syncthreads();
    if (half == 0 && g < G) {
        out[(long)b * G + g] = result + red[gl];
    }
}

extern "C" void kernel_launch(void* const* d_in, const int* in_sizes, int n_in,
                              void* d_out, int out_size) {
    const float* R      = (const float*)d_in[0];  // (B, A, 3) f32
    const float* coords = (const float*)d_in[1];  // (G, 3)    f32
    const float* W      = (const float*)d_in[2];  // (3, 3)    f32

    const int A = in_sizes[3];
    const int B = in_sizes[0] / (3 * A);
    const int G = in_sizes[1] / 3;

    float* out = (float*)d_out;  // (B, G) f32

    dim3 grid((G + GPB - 1) / GPB, B);
    size_t smem = (size_t)A * sizeof(float4) + GPB * sizeof(float);

    initlayer_kernel<<<grid, 256, smem>>>(R, coords, W, out, A, G);
}

// round 5
// speedup vs baseline: 1.1810x; 1.0980x over previous
#include <cuda_runtime.h>
#include <cuda_bf16.h>

#define LOG2E 1.4426950408889634f

typedef unsigned long long u64;

__device__ __forceinline__ u64 pk2(float lo, float hi) {
    u64 r; asm("mov.b64 %0, {%1, %2};" : "=l"(r) : "f"(lo), "f"(hi)); return r;
}
__device__ __forceinline__ void upk2(float& lo, float& hi, u64 v) {
    asm("mov.b64 {%0, %1}, %2;" : "=f"(lo), "=f"(hi) : "l"(v));
}
__device__ __forceinline__ u64 ffma2(u64 a, u64 b, u64 c) {
    u64 d; asm("fma.rn.f32x2 %0, %1, %2, %3;" : "=l"(d) : "l"(a), "l"(b), "l"(c)); return d;
}
__device__ __forceinline__ u64 fadd2(u64 a, u64 b) {
    u64 d; asm("add.rn.f32x2 %0, %1, %2;" : "=l"(d) : "l"(a), "l"(b)); return d;
}
__device__ __forceinline__ float sqrt_ap(float x) {
    float d; asm("sqrt.approx.f32 %0, %1;" : "=f"(d) : "f"(x)); return d;
}
__device__ __forceinline__ float ex2_ap(float x) {
    float e; asm("ex2.approx.f32 %0, %1;" : "=f"(e) : "f"(x)); return e;
}

#define GPB 128  // grid points per block; 256 threads = 2 atom-halves per g

__global__ __launch_bounds__(256, 8)  // force regs<=32: 8 CTAs/SM -> single wave
void initlayer_kernel(const float* __restrict__ R,
                      const float* __restrict__ coords,
                      const float* __restrict__ W,
                      float* __restrict__ out,
                      int A, int G) {
    // Pair-packed atoms: sm4[2p]   = (px0,px1,py0,py1)
    //                    sm4[2p+1] = (pz0,pz1,pw0,pw1),  pw = |p'|^2
    extern __shared__ float smem[];
    float4* sm4 = (float4*)smem;
    const int npairs_alloc = (256 + 1) / 2;  // placeholder; real offset below uses A
    (void)npairs_alloc;
    float* red = smem + ((A + 1) / 2) * 8;   // GPB floats: partial-sum exchange

    const int tid  = threadIdx.x;
    const int b    = blockIdx.y;
    const int gl   = tid & (GPB - 1);
    const int half = tid >> 7;
    const int g    = blockIdx.x * GPB + gl;

    // Weight pre-scaled by log2(e): exp(||W(c-r)||) == ex2(||W'(c-r)||).
    const float w00 = W[0] * LOG2E, w01 = W[1] * LOG2E, w02 = W[2] * LOG2E;
    const float w10 = W[3] * LOG2E, w11 = W[4] * LOG2E, w12 = W[5] * LOG2E;
    const float w20 = W[6] * LOG2E, w21 = W[7] * LOG2E, w22 = W[8] * LOG2E;

    // Prologue: transform atoms, store pair-packed (p', |p'|^2).
    for (int a = tid; a < A; a += blockDim.x) {
        const float* r = R + ((long)b * A + a) * 3;
        float rx = r[0], ry = r[1], rz = r[2];
        float px = fmaf(w00, rx, fmaf(w01, ry, w02 * rz));
        float py = fmaf(w10, rx, fmaf(w11, ry, w12 * rz));
        float pz = fmaf(w20, rx, fmaf(w21, ry, w22 * rz));
        float pw = fmaf(px, px, fmaf(py, py, pz * pz));
        float* base = smem + (a >> 1) * 8;
        int h = a & 1;
        base[0 + h] = px;
        base[2 + h] = py;
        base[4 + h] = pz;
        base[6 + h] = pw;
    }
    __syncthreads();

    float result = 0.0f;
    if (g < G) {
        const float cx = coords[g * 3 + 0];
        const float cy = coords[g * 3 + 1];
        const float cz = coords[g * 3 + 2];
        const float qx = fmaf(w00, cx, fmaf(w01, cy, w02 * cz));
        const float qy = fmaf(w10, cx, fmaf(w11, cy, w12 * cz));
        const float qz = fmaf(w20, cx, fmaf(w21, cy, w22 * cz));
        const float qn = fmaf(qx, qx, fmaf(qy, qy, qz * qz));

        const u64 m2x2 = pk2(-2.0f * qx, -2.0f * qx);
        const u64 m2y2 = pk2(-2.0f * qy, -2.0f * qy);
        const u64 m2z2 = pk2(-2.0f * qz, -2.0f * qz);
        const u64 qn2  = pk2(qn, qn);

        // This thread's atom range [a0, a1): halves of A.
        const int ahalf = A >> 1;
        const int a0 = half ? ahalf : 0;
        const int a1 = half ? A : ahalf;
        // Pair range fully inside [a0, a1):
        int p0 = (a0 + 1) >> 1;
        int p1 = a1 >> 1;

        float acc0 = 0.0f, acc1 = 0.0f, acc2 = 0.0f, acc3 = 0.0f;

        int p = p0;
        #pragma unroll 4
        for (; p + 2 <= p1; p += 2) {
            {
                float4 PA = sm4[2 * p + 0];
                float4 PB = sm4[2 * p + 1];
                u64 u = fadd2(pk2(PB.z, PB.w), qn2);          // pw + qn
                u = ffma2(m2z2, pk2(PB.x, PB.y), u);
                u = ffma2(m2y2, pk2(PA.z, PA.w), u);
                u = ffma2(m2x2, pk2(PA.x, PA.y), u);
                float s0, s1; upk2(s0, s1, u);
                acc0 += ex2_ap(sqrt_ap(fmaxf(s0, 0.0f)));
                acc1 += ex2_ap(sqrt_ap(fmaxf(s1, 0.0f)));
            }
            {
                float4 PA = sm4[2 * p + 2];
                float4 PB = sm4[2 * p + 3];
                u64 u = fadd2(pk2(PB.z, PB.w), qn2);
                u = ffma2(m2z2, pk2(PB.x, PB.y), u);
                u = ffma2(m2y2, pk2(PA.z, PA.w), u);
                u = ffma2(m2x2, pk2(PA.x, PA.y), u);
                float s0, s1; upk2(s0, s1, u);
                acc2 += ex2_ap(sqrt_ap(fmaxf(s0, 0.0f)));
                acc3 += ex2_ap(sqrt_ap(fmaxf(s1, 0.0f)));
            }
        }
        for (; p < p1; ++p) {
            float4 PA = sm4[2 * p + 0];
            float4 PB = sm4[2 * p + 1];
            u64 u = fadd2(pk2(PB.z, PB.w), qn2);
            u = ffma2(m2z2, pk2(PB.x, PB.y), u);
            u = ffma2(m2y2, pk2(PA.z, PA.w), u);
            u = ffma2(m2x2, pk2(PA.x, PA.y), u);
            float s0, s1; upk2(s0, s1, u);
            acc0 += ex2_ap(sqrt_ap(fmaxf(s0, 0.0f)));
            acc1 += ex2_ap(sqrt_ap(fmaxf(s1, 0.0f)));
        }
        // Scalar tail: atoms in [a0,a1) not covered by pairs [p0,p1).
        for (int a = a0; a < 2 * p0 && a < a1; ++a) {
            float* base = smem + (a >> 1) * 8;
            int h = a & 1;
            float s = fmaf(-2.0f * qx, base[0 + h],
                      fmaf(-2.0f * qy, base[2 + h],
                      fmaf(-2.0f * qz, base[4 + h], qn + base[6 + h])));
            acc0 += ex2_ap(sqrt_ap(fmaxf(s, 0.0f)));
        }
        for (int a = 2 * p1 > a0 ? 2 * p1 : a0; a < a1; ++a) {
            float* base = smem + (a >> 1) * 8;
            int h = a & 1;
            float s = fmaf(-2.0f * qx, base[0 + h],
                      fmaf(-2.0f * qy, base[2 + h],
                      fmaf(-2.0f * qz, base[4 + h], qn + base[6 + h])));
            acc0 += ex2_ap(sqrt_ap(fmaxf(s, 0.0f)));
        }
        result = (acc0 + acc1) + (acc2 + acc3);
    }

    // Combine the two atom-half partials; single writer per g.
    if (half == 1) red[gl] = result;
    __syncthreads();
    if (half == 0 && g < G) {
        out[(long)b * G + g] = result + red[gl];
    }
}

extern "C" void kernel_launch(void* const* d_in, const int* in_sizes, int n_in,
                              void* d_out, int out_size) {
    const float* R      = (const float*)d_in[0];  // (B, A, 3) f32
    const float* coords = (const float*)d_in[1];  // (G, 3)    f32
    const float* W      = (const float*)d_in[2];  // (3, 3)    f32

    const int A = in_sizes[3];
    const int B = in_sizes[0] / (3 * A);
    const int G = in_sizes[1] / 3;

    float* out = (float*)d_out;  // (B, G) f32

    dim3 grid((G + GPB - 1) / GPB, B);
    size_t smem = (size_t)((A + 1) / 2) * 8 * sizeof(float) + GPB * sizeof(float);

    initlayer_kernel<<<grid, 256, smem>>>(R, coords, W, out, A, G);
}

// round 6
// speedup vs baseline: 1.1954x; 1.0122x over previous
#include <cuda_runtime.h>
#include <cuda_bf16.h>

#define LOG2E 1.4426950408889634f

typedef unsigned long long u64;

__device__ __forceinline__ void upk2(float& lo, float& hi, u64 v) {
    asm("mov.b64 {%0, %1}, %2;" : "=f"(lo), "=f"(hi) : "l"(v));
}
__device__ __forceinline__ u64 pk2(float lo, float hi) {
    u64 r; asm("mov.b64 %0, {%1, %2};" : "=l"(r) : "f"(lo), "f"(hi)); return r;
}
__device__ __forceinline__ u64 ffma2(u64 a, u64 b, u64 c) {
    u64 d; asm("fma.rn.f32x2 %0, %1, %2, %3;" : "=l"(d) : "l"(a), "l"(b), "l"(c)); return d;
}
__device__ __forceinline__ u64 fadd2(u64 a, u64 b) {
    u64 d; asm("add.rn.f32x2 %0, %1, %2;" : "=l"(d) : "l"(a), "l"(b)); return d;
}
__device__ __forceinline__ float sqrt_ap(float x) {
    float d; asm("sqrt.approx.f32 %0, %1;" : "=f"(d) : "f"(x)); return d;
}
__device__ __forceinline__ float ex2_ap(float x) {
    float e; asm("ex2.approx.f32 %0, %1;" : "=f"(e) : "f"(x)); return e;
}
// exp(d) of one packed squared-distance pair -> two accumulator adds.
// |s| instead of max(s,0): tiny-negative cancellation -> sqrt(|s|)~0, exp~1,
// identical within tolerance; abs folds into the MUFU source modifier.
__device__ __forceinline__ void pair_exp(u64 u, float& accA, float& accB) {
    float s0, s1; upk2(s0, s1, u);
    accA += ex2_ap(sqrt_ap(fabsf(s0)));
    accB += ex2_ap(sqrt_ap(fabsf(s1)));
}

#define GPB 128  // grid points per block; 256 threads = 2 atom-halves per g

__global__ __launch_bounds__(256, 8)
void initlayer_kernel(const float* __restrict__ R,
                      const float* __restrict__ coords,
                      const float* __restrict__ W,
                      float* __restrict__ out,
                      int A, int G) {
    // Pair-packed atoms, 32B per pair:
    //   [p].x=(px0,px1) [p].y=(py0,py1) | [p].z=(pz0,pz1) [p].w=(pw0,pw1)
    extern __shared__ float smem[];
    const ulonglong2* smp = (const ulonglong2*)smem;
    float* red = smem + ((A + 1) / 2) * 8;   // GPB floats: partial-sum exchange

    const int tid  = threadIdx.x;
    const int b    = blockIdx.y;
    const int gl   = tid & (GPB - 1);
    const int half = tid >> 7;
    const int g    = blockIdx.x * GPB + gl;

    // Weight pre-scaled by log2(e): exp(||W(c-r)||) == ex2(||W'(c-r)||).
    const float w00 = W[0] * LOG2E, w01 = W[1] * LOG2E, w02 = W[2] * LOG2E;
    const float w10 = W[3] * LOG2E, w11 = W[4] * LOG2E, w12 = W[5] * LOG2E;
    const float w20 = W[6] * LOG2E, w21 = W[7] * LOG2E, w22 = W[8] * LOG2E;

    // Prologue: transform atoms, store pair-packed (p', |p'|^2).
    for (int a = tid; a < A; a += blockDim.x) {
        const float* r = R + ((long)b * A + a) * 3;
        float rx = r[0], ry = r[1], rz = r[2];
        float px = fmaf(w00, rx, fmaf(w01, ry, w02 * rz));
        float py = fmaf(w10, rx, fmaf(w11, ry, w12 * rz));
        float pz = fmaf(w20, rx, fmaf(w21, ry, w22 * rz));
        float pw = fmaf(px, px, fmaf(py, py, pz * pz));
        float* base = smem + (a >> 1) * 8;
        int h = a & 1;
        base[0 + h] = px;
        base[2 + h] = py;
        base[4 + h] = pz;
        base[6 + h] = pw;
    }
    __syncthreads();

    float result = 0.0f;
    if (g < G) {
        const float cx = coords[g * 3 + 0];
        const float cy = coords[g * 3 + 1];
        const float cz = coords[g * 3 + 2];
        const float qx = fmaf(w00, cx, fmaf(w01, cy, w02 * cz));
        const float qy = fmaf(w10, cx, fmaf(w11, cy, w12 * cz));
        const float qz = fmaf(w20, cx, fmaf(w21, cy, w22 * cz));
        const float qn = fmaf(qx, qx, fmaf(qy, qy, qz * qz));

        const u64 m2x2 = pk2(-2.0f * qx, -2.0f * qx);
        const u64 m2y2 = pk2(-2.0f * qy, -2.0f * qy);
        const u64 m2z2 = pk2(-2.0f * qz, -2.0f * qz);
        const u64 qn2  = pk2(qn, qn);

        // This thread's atom half [a0, a1); pair indices [p0, p1).
        const int ahalf = A >> 1;
        const int a0 = half ? ahalf : 0;
        const int a1 = half ? A : ahalf;
        const int p0 = (a0 + 1) >> 1;
        const int p1 = a1 >> 1;

        float acc0 = 0.0f, acc1 = 0.0f, acc2 = 0.0f, acc3 = 0.0f;

        int p = p0;
        for (; p + 4 <= p1; p += 4) {
            // operands load directly as packed u64 pairs: no MOVs
            ulonglong2 A0 = smp[2 * p + 0], B0 = smp[2 * p + 1];
            ulonglong2 A1 = smp[2 * p + 2], B1 = smp[2 * p + 3];
            ulonglong2 A2 = smp[2 * p + 4], B2 = smp[2 * p + 5];
            ulonglong2 A3 = smp[2 * p + 6], B3 = smp[2 * p + 7];

            u64 u0 = fadd2(B0.y, qn2);
            u0 = ffma2(m2z2, B0.x, u0);
            u0 = ffma2(m2y2, A0.y, u0);
            u0 = ffma2(m2x2, A0.x, u0);

            u64 u1 = fadd2(B1.y, qn2);
            u1 = ffma2(m2z2, B1.x, u1);
            u1 = ffma2(m2y2, A1.y, u1);
            u1 = ffma2(m2x2, A1.x, u1);

            u64 u2 = fadd2(B2.y, qn2);
            u2 = ffma2(m2z2, B2.x, u2);
            u2 = ffma2(m2y2, A2.y, u2);
            u2 = ffma2(m2x2, A2.x, u2);

            u64 u3 = fadd2(B3.y, qn2);
            u3 = ffma2(m2z2, B3.x, u3);
            u3 = ffma2(m2y2, A3.y, u3);
            u3 = ffma2(m2x2, A3.x, u3);

            pair_exp(u0, acc0, acc1);
            pair_exp(u1, acc2, acc3);
            pair_exp(u2, acc0, acc1);
            pair_exp(u3, acc2, acc3);
        }
        for (; p < p1; ++p) {
            ulonglong2 PA = smp[2 * p + 0], PB = smp[2 * p + 1];
            u64 u = fadd2(PB.y, qn2);
            u = ffma2(m2z2, PB.x, u);
            u = ffma2(m2y2, PA.y, u);
            u = ffma2(m2x2, PA.x, u);
            pair_exp(u, acc0, acc1);
        }
        // Scalar tails (odd boundaries; no-ops for A=256 halves).
        for (int a = a0; a < 2 * p0 && a < a1; ++a) {
            const float* base = smem + (a >> 1) * 8;
            int h = a & 1;
            float s = fmaf(-2.0f * qx, base[0 + h],
                      fmaf(-2.0f * qy, base[2 + h],
                      fmaf(-2.0f * qz, base[4 + h], qn + base[6 + h])));
            acc0 += ex2_ap(sqrt_ap(fabsf(s)));
        }
        for (int a = (2 * p1 > a0 ? 2 * p1 : a0); a < a1; ++a) {
            const float* base = smem + (a >> 1) * 8;
            int h = a & 1;
            float s = fmaf(-2.0f * qx, base[0 + h],
                      fmaf(-2.0f * qy, base[2 + h],
                      fmaf(-2.0f * qz, base[4 + h], qn + base[6 + h])));
            acc0 += ex2_ap(sqrt_ap(fabsf(s)));
        }
        result = (acc0 + acc1) + (acc2 + acc3);
    }

    // Combine the two atom-half partials; single writer per g.
    if (half == 1) red[gl] = result;
    __syncthreads();
    if (half == 0 && g < G) {
        out[(long)b * G + g] = result + red[gl];
    }
}

extern "C" void kernel_launch(void* const* d_in, const int* in_sizes, int n_in,
                              void* d_out, int out_size) {
    const float* R      = (const float*)d_in[0];  // (B, A, 3) f32
    const float* coords = (const float*)d_in[1];  // (G, 3)    f32
    const float* W      = (const float*)d_in[2];  // (3, 3)    f32

    const int A = in_sizes[3];
    const int B = in_sizes[0] / (3 * A);
    const int G = in_sizes[1] / 3;

    float* out = (float*)d_out;  // (B, G) f32

    dim3 grid((G + GPB - 1) / GPB, B);
    size_t smem = (size_t)((A + 1) / 2) * 8 * sizeof(float) + GPB * sizeof(float);

    initlayer_kernel<<<grid, 256, smem>>>(R, coords, W, out, A, G);
}